// round 5
// baseline (speedup 1.0000x reference)
#include <cuda_runtime.h>

namespace {

constexpr int THREADS = 384;   // 12 warps
constexpr int NW = 12;

__device__ __align__(16) float g_W1p[27 * 128];  // W1 transposed: [k][j]
__device__ __align__(16) float g_Wsum[9 * 128];  // W1p[d]+W1p[9+d]+W1p[18+d]

__global__ void prep_kernel(const float* __restrict__ W1) {
    int j = threadIdx.x;  // 0..127
    #pragma unroll
    for (int k = 0; k < 27; k++) g_W1p[k * 128 + j] = W1[j * 27 + k];
    #pragma unroll
    for (int d = 0; d < 9; d++)
        g_Wsum[d * 128 + j] = W1[j * 27 + d] + W1[j * 27 + 9 + d] + W1[j * 27 + 18 + d];
}

// Integer redux is supported on sm_103 (sm_80+); f32 redux is not.
__device__ __forceinline__ unsigned redux_maxu(unsigned v) {
    unsigned r; asm("redux.sync.max.u32 %0, %1, 0xffffffff;" : "=r"(r) : "r"(v)); return r;
}
__device__ __forceinline__ unsigned redux_minu(unsigned v) {
    unsigned r; asm("redux.sync.min.u32 %0, %1, 0xffffffff;" : "=r"(r) : "r"(v)); return r;
}

__global__ __launch_bounds__(THREADS, 5)
void sudoku_kernel(const float* __restrict__ x,
                   const float* __restrict__ W2,
                   float* __restrict__ out)
{
    __shared__ __align__(16) float zs[81 * 128];  // cached pre-activations (float4/lane)
    __shared__ float cnt[3][9][9];
    __shared__ float score_s[96];                 // 81 used; padding reads 0
    __shared__ int   pos_s[81];
    __shared__ unsigned char emptyb[81];

    const int tid  = threadIdx.x;
    const int lane = tid & 31;
    const int wid  = tid >> 5;
    const long long b = blockIdx.x;
    const float* xb = x + b * 729;
    float* ob = out + b * 729;

    // W2 in registers: lane owns hidden units 4*lane .. 4*lane+3
    float4 w2r[9];
    #pragma unroll
    for (int e = 0; e < 9; e++)
        w2r[e] = __ldg((const float4*)(W2 + e * 128) + lane);

    for (int i = tid; i < 243; i += THREADS) (&cnt[0][0][0])[i] = 0.f;
    for (int i = tid; i < 729; i += THREADS) ob[i] = xb[i];   // x_pred init = x
    if (tid < 96) score_s[tid] = 0.f;
    __syncthreads();

    if (tid < 81) {
        int d = -1;
        #pragma unroll
        for (int e = 0; e < 9; e++)
            if (xb[tid * 9 + e] > 0.5f) d = e;
        pos_s[tid] = 0;
        if (d >= 0) {
            emptyb[tid] = 0;
            int r = tid / 9, c = tid % 9, bx = (r / 3) * 3 + c / 3;
            atomicAdd(&cnt[0][r][d],  1.f);
            atomicAdd(&cnt[1][c][d],  1.f);
            atomicAdd(&cnt[2][bx][d], 1.f);
        } else {
            emptyb[tid] = 1;
        }
    }
    __syncthreads();

    // relu(z) @ W2^T via XOR butterfly (all lanes get full y), then fully
    // redundant per-lane softmax. Math identical to R4 (keeps rel_err behavior).
    auto compute_y = [&](int c, float4 z) {
        float h0 = fmaxf(z.x, 0.f), h1 = fmaxf(z.y, 0.f);
        float h2 = fmaxf(z.z, 0.f), h3 = fmaxf(z.w, 0.f);
        float p[9];
        #pragma unroll
        for (int e = 0; e < 9; e++) {
            float a = h0 * w2r[e].x;
            a = fmaf(h1, w2r[e].y, a);
            a = fmaf(h2, w2r[e].z, a);
            a = fmaf(h3, w2r[e].w, a);
            p[e] = a;
        }
        #pragma unroll
        for (int off = 16; off > 0; off >>= 1) {
            #pragma unroll
            for (int e = 0; e < 9; e++)
                p[e] += __shfl_xor_sync(0xffffffffu, p[e], off);
        }
        float mx = p[0];
        #pragma unroll
        for (int e = 1; e < 9; e++) mx = fmaxf(mx, p[e]);
        float q[9], sum = 0.f;
        #pragma unroll
        for (int e = 0; e < 9; e++) { q[e] = expf(p[e] - mx); sum += q[e]; }
        float best = q[0]; int bp = 0;
        #pragma unroll
        for (int e = 1; e < 9; e++)
            if (q[e] > best) { best = q[e]; bp = e; }   // strict > = first max
        if (lane < 9) ob[c * 9 + lane] = q[lane] / sum;
        if (lane == 0) { score_s[c] = best / sum; pos_s[c] = bp; }
    };

    // Initial full pass: fresh z for every empty cell
    for (int c = wid; c < 81; c += NW) {
        if (!emptyb[c]) continue;
        float4 z = make_float4(0.f, 0.f, 0.f, 0.f);
        if (c < 27) {                        // row consumer: 3x-replicated f -> Wsum
            const float* cp = cnt[0][c / 3];
            #pragma unroll
            for (int e = 0; e < 9; e++) {
                float fv = cp[e];
                float4 w = __ldg((const float4*)(g_Wsum + e * 128) + lane);
                z.x = fmaf(fv, w.x, z.x); z.y = fmaf(fv, w.y, z.y);
                z.z = fmaf(fv, w.z, z.z); z.w = fmaf(fv, w.w, z.w);
            }
        } else if (c < 54) {                 // column consumer: 3 distinct groups
            int g0 = 3 * ((c - 27) % 3);
            #pragma unroll
            for (int blk = 0; blk < 3; blk++) {
                const float* cp = cnt[1][g0 + blk];
                #pragma unroll
                for (int e = 0; e < 9; e++) {
                    float fv = cp[e];
                    float4 w = __ldg((const float4*)(g_W1p + (9 * blk + e) * 128) + lane);
                    z.x = fmaf(fv, w.x, z.x); z.y = fmaf(fv, w.y, z.y);
                    z.z = fmaf(fv, w.z, z.z); z.w = fmaf(fv, w.w, z.w);
                }
            }
        } else {                             // box consumer: 3x-replicated f -> Wsum
            int u = c - 54;
            const float* cp = cnt[2][3 * (u / 9) + u % 3];
            #pragma unroll
            for (int e = 0; e < 9; e++) {
                float fv = cp[e];
                float4 w = __ldg((const float4*)(g_Wsum + e * 128) + lane);
                z.x = fmaf(fv, w.x, z.x); z.y = fmaf(fv, w.y, z.y);
                z.z = fmaf(fv, w.z, z.z); z.w = fmaf(fv, w.w, z.w);
            }
        }
        *((float4*)(zs + c * 128) + lane) = z;
        compute_y(c, z);
    }

    // Sequential fill loop. Two barriers/iter: A orders prior-iter writes before
    // selection reads; B orders selection reads before this iter's state writes.
    for (int iter = 0; iter < 81; ++iter) {
        __syncthreads();   // A

        float s0 = score_s[lane];
        float s1 = score_s[lane + 32];
        float s2 = score_s[lane + 64];      // padded region (>=81) reads 0
        unsigned bb = __float_as_uint(s0); int bi = lane;
        unsigned v1 = __float_as_uint(s1); if (v1 > bb) { bb = v1; bi = lane + 32; }
        unsigned v2 = __float_as_uint(s2); if (v2 > bb) { bb = v2; bi = lane + 64; }
        unsigned wmax = redux_maxu(bb);
        if (wmax == 0u) break;              // uniform across all warps
        unsigned cand = (bb == wmax) ? (unsigned)bi : 0xFFu;
        const int m = (int)redux_minu(cand);   // global first-max index
        const int d = pos_s[m];

        __syncthreads();   // B — selection reads complete before any writes
        if (tid == 0) { emptyb[m] = 0; score_s[m] = 0.f; }

        const int rm = m / 9, cm = m % 9;
        const int cm3 = cm / 3, brm = (rm / 3) * 3;

        const float4 wsum4 = __ldg((const float4*)(g_Wsum + d * 128) + lane);
        const float4 wcol4 = __ldg((const float4*)(g_W1p + (9 * (cm % 3) + d) * 128) + lane);

        // 15 affected output rows (disjoint: 3 row, 9 col, 3 box), warp-per-cell
        #pragma unroll
        for (int rep = 0; rep < 2; rep++) {
            int i = wid + rep * NW;
            if (i >= 15) break;
            int c; float4 w;
            if (i < 3)       { c = 3 * rm + i;                      w = wsum4; }
            else if (i < 12) { c = 27 + 3 * (i - 3) + cm3;          w = wcol4; }
            else             { c = 54 + 3 * (brm + (i - 12)) + cm3; w = wsum4; }
            if (c == m || !emptyb[c]) continue;   // c==m checked first (race-free)
            float4* zp = (float4*)(zs + c * 128) + lane;
            float4 z = *zp;
            z.x += w.x; z.y += w.y; z.z += w.z; z.w += w.w;
            *zp = z;
            compute_y(c, z);
        }
    }
}

} // namespace

extern "C" void kernel_launch(void* const* d_in, const int* in_sizes, int n_in,
                              void* d_out, int out_size) {
    const float* x  = (const float*)d_in[0];
    const float* W1 = (const float*)d_in[1];
    const float* W2 = (const float*)d_in[2];
    float* out = (float*)d_out;
    int B = in_sizes[0] / 729;
    prep_kernel<<<1, 128>>>(W1);
    sudoku_kernel<<<B, THREADS>>>(x, W2, out);
}

// round 6
// speedup vs baseline: 1.8868x; 1.8868x over previous
#include <cuda_runtime.h>

namespace {

constexpr int THREADS = 160;   // 5 warps
constexpr int NW = 5;
constexpr int MAXB = 2048;

__device__ __align__(16) float g_W1p[27 * 128];   // W1 transposed: [k][j]
__device__ __align__(16) float g_Wsum[9 * 128];   // W1p[d]+W1p[9+d]+W1p[18+d]
__device__ float4 g_zs[(size_t)MAXB * 81 * 32];   // per-board pre-activation scratch

__global__ void prep_kernel(const float* __restrict__ W1) {
    int j = threadIdx.x;  // 0..127
    #pragma unroll
    for (int k = 0; k < 27; k++) g_W1p[k * 128 + j] = W1[j * 27 + k];
    #pragma unroll
    for (int d = 0; d < 9; d++)
        g_Wsum[d * 128 + j] = W1[j * 27 + d] + W1[j * 27 + 9 + d] + W1[j * 27 + 18 + d];
}

// Integer redux is supported on sm_103; f32 redux is not.
__device__ __forceinline__ unsigned redux_maxu(unsigned v) {
    unsigned r; asm("redux.sync.max.u32 %0, %1, 0xffffffff;" : "=r"(r) : "r"(v)); return r;
}
__device__ __forceinline__ unsigned redux_minu(unsigned v) {
    unsigned r; asm("redux.sync.min.u32 %0, %1, 0xffffffff;" : "=r"(r) : "r"(v)); return r;
}

__global__ __launch_bounds__(THREADS, 8)
void sudoku_kernel(const float* __restrict__ x,
                   const float* __restrict__ W2,
                   float* __restrict__ out)
{
    __shared__ float4 w2s[9 * 32];        // W2 rows as float4 per lane
    __shared__ float cnt[3][9][9];
    __shared__ float score_s[96];         // 81 used; padding reads 0
    __shared__ int   pos_s[81];
    __shared__ unsigned char emptyb[81];
    __shared__ unsigned char empty0[81];  // initial-empty flags (for final pass)

    const int tid  = threadIdx.x;
    const int lane = tid & 31;
    const int wid  = tid >> 5;
    const long long b = blockIdx.x;
    const float* xb = x + b * 729;
    float* ob = out + b * 729;
    float4* zb = g_zs + (size_t)b * 81 * 32;

    for (int i = tid; i < 288; i += THREADS) w2s[i] = ((const float4*)W2)[i];
    for (int i = tid; i < 243; i += THREADS) (&cnt[0][0][0])[i] = 0.f;
    for (int i = tid; i < 729; i += THREADS) ob[i] = xb[i];   // x_pred init = x
    if (tid < 96) score_s[tid] = 0.f;
    __syncthreads();

    if (tid < 81) {
        int d = -1;
        #pragma unroll
        for (int e = 0; e < 9; e++)
            if (xb[tid * 9 + e] > 0.5f) d = e;
        pos_s[tid] = 0;
        if (d >= 0) {
            emptyb[tid] = 0; empty0[tid] = 0;
            int r = tid / 9, c = tid % 9, bx = (r / 3) * 3 + c / 3;
            atomicAdd(&cnt[0][r][d],  1.f);
            atomicAdd(&cnt[1][c][d],  1.f);
            atomicAdd(&cnt[2][bx][d], 1.f);
        } else {
            emptyb[tid] = 1; empty0[tid] = 1;
        }
    }
    __syncthreads();

    // relu(z) @ W2^T + XOR butterfly: all lanes end with the full 9-vector p.
    auto reduce_p = [&](float4 z, float p[9]) {
        float h0 = fmaxf(z.x, 0.f), h1 = fmaxf(z.y, 0.f);
        float h2 = fmaxf(z.z, 0.f), h3 = fmaxf(z.w, 0.f);
        #pragma unroll
        for (int e = 0; e < 9; e++) {
            float4 w = w2s[e * 32 + lane];
            float a = h0 * w.x;
            a = fmaf(h1, w.y, a);
            a = fmaf(h2, w.z, a);
            a = fmaf(h3, w.w, a);
            p[e] = a;
        }
        #pragma unroll
        for (int off = 16; off > 0; off >>= 1) {
            #pragma unroll
            for (int e = 0; e < 9; e++)
                p[e] += __shfl_xor_sync(0xffffffffu, p[e], off);
        }
    };

    // In-loop: only score (max softmax prob) + argmax; no output writes.
    auto score_from_p = [&](int c, const float p[9]) {
        float mx = p[0];
        #pragma unroll
        for (int e = 1; e < 9; e++) mx = fmaxf(mx, p[e]);
        float sum = 0.f, best = -1.f; int bp = 0;
        #pragma unroll
        for (int e = 0; e < 9; e++) {
            float q = expf(p[e] - mx);
            sum += q;
            if (q > best) { best = q; bp = e; }   // strict > = first max
        }
        if (lane == 0) { score_s[c] = best / sum; pos_s[c] = bp; }
    };

    // map affected-slot index (0..14) -> cell id
    auto map_cell = [](int i, int rm, int cm3, int brm) -> int {
        if (i < 3)  return 3 * rm + i;
        if (i < 12) return 27 + 3 * (i - 3) + cm3;
        return 54 + 3 * (brm + (i - 12)) + cm3;
    };

    // Initial full pass: fresh z for every empty cell
    for (int c = wid; c < 81; c += NW) {
        if (!emptyb[c]) continue;
        float4 z = make_float4(0.f, 0.f, 0.f, 0.f);
        if (c < 27) {
            const float* cp = cnt[0][c / 3];
            #pragma unroll
            for (int e = 0; e < 9; e++) {
                float fv = cp[e];
                float4 w = __ldg((const float4*)(g_Wsum + e * 128) + lane);
                z.x = fmaf(fv, w.x, z.x); z.y = fmaf(fv, w.y, z.y);
                z.z = fmaf(fv, w.z, z.z); z.w = fmaf(fv, w.w, z.w);
            }
        } else if (c < 54) {
            int g0 = 3 * ((c - 27) % 3);
            #pragma unroll
            for (int blk = 0; blk < 3; blk++) {
                const float* cp = cnt[1][g0 + blk];
                #pragma unroll
                for (int e = 0; e < 9; e++) {
                    float fv = cp[e];
                    float4 w = __ldg((const float4*)(g_W1p + (9 * blk + e) * 128) + lane);
                    z.x = fmaf(fv, w.x, z.x); z.y = fmaf(fv, w.y, z.y);
                    z.z = fmaf(fv, w.z, z.z); z.w = fmaf(fv, w.w, z.w);
                }
            }
        } else {
            int u = c - 54;
            const float* cp = cnt[2][3 * (u / 9) + u % 3];
            #pragma unroll
            for (int e = 0; e < 9; e++) {
                float fv = cp[e];
                float4 w = __ldg((const float4*)(g_Wsum + e * 128) + lane);
                z.x = fmaf(fv, w.x, z.x); z.y = fmaf(fv, w.y, z.y);
                z.z = fmaf(fv, w.z, z.z); z.w = fmaf(fv, w.w, z.w);
            }
        }
        zb[c * 32 + lane] = z;
        float p[9];
        reduce_p(z, p);
        score_from_p(c, p);
    }

    // Sequential fill loop
    for (int iter = 0; iter < 81; ++iter) {
        __syncthreads();   // A: prior-iter writes visible to all

        float s0 = score_s[lane];
        float s1 = score_s[lane + 32];
        float s2 = score_s[lane + 64];
        unsigned bb = __float_as_uint(s0); int bi = lane;
        unsigned v1 = __float_as_uint(s1); if (v1 > bb) { bb = v1; bi = lane + 32; }
        unsigned v2 = __float_as_uint(s2); if (v2 > bb) { bb = v2; bi = lane + 64; }
        unsigned wmax = redux_maxu(bb);
        if (wmax == 0u) break;              // uniform across block
        unsigned cand = (bb == wmax) ? (unsigned)bi : 0xFFu;
        const int m = (int)redux_minu(cand);
        const int d = pos_s[m];

        const int rm = m / 9, cm = m % 9;
        const int cm3 = cm / 3, brm = (rm / 3) * 3;

        // compacted empty-affected mask (identical in every warp)
        int cl = map_cell(lane < 15 ? lane : 0, rm, cm3, brm);
        bool pred = (lane < 15) && (cl != m) && emptyb[cl];
        unsigned mask = __ballot_sync(0xffffffffu, pred);
        int nempty = __popc(mask);

        // prefetch this warp's first cell's z (safe: prior z-writes ordered by A)
        int bit0 = 0, c0 = 0; float4 zpre;
        if (wid < nempty) {
            bit0 = __fns(mask, 0, wid + 1);
            c0 = map_cell(bit0, rm, cm3, brm);
            zpre = zb[c0 * 32 + lane];
        }
        const float4 wsum4 = __ldg((const float4*)(g_Wsum + d * 128) + lane);
        const float4 wcol4 = __ldg((const float4*)(g_W1p + (9 * (cm % 3) + d) * 128) + lane);

        __syncthreads();   // B: selection/mask reads done before state writes
        if (tid == 0) { emptyb[m] = 0; score_s[m] = 0.f; }

        for (int idx = wid; idx < nempty; idx += NW) {
            int bit = (idx == wid) ? bit0 : (int)__fns(mask, 0, idx + 1);
            int c   = (idx == wid) ? c0   : map_cell(bit, rm, cm3, brm);
            float4 w = (bit >= 3 && bit < 12) ? wcol4 : wsum4;
            float4 z = (idx == wid) ? zpre : zb[c * 32 + lane];
            z.x += w.x; z.y += w.y; z.z += w.z; z.w += w.w;
            zb[c * 32 + lane] = z;
            float p[9];
            reduce_p(z, p);
            score_from_p(c, p);
        }
    }
    __syncthreads();

    // Final pass: softmax of frozen z for every initially-empty cell.
    // (x_pred for each such cell = softmax at its last empty-state z, which is
    //  exactly the frozen z; never-empty cells keep x.)
    for (int c = wid; c < 81; c += NW) {
        if (!empty0[c]) continue;
        float4 z = zb[c * 32 + lane];
        float p[9];
        reduce_p(z, p);
        float mx = p[0];
        #pragma unroll
        for (int e = 1; e < 9; e++) mx = fmaxf(mx, p[e]);
        float q[9], sum = 0.f;
        #pragma unroll
        for (int e = 0; e < 9; e++) { q[e] = expf(p[e] - mx); sum += q[e]; }
        if (lane < 9) ob[c * 9 + lane] = q[lane] / sum;
    }
}

} // namespace

extern "C" void kernel_launch(void* const* d_in, const int* in_sizes, int n_in,
                              void* d_out, int out_size) {
    const float* x  = (const float*)d_in[0];
    const float* W1 = (const float*)d_in[1];
    const float* W2 = (const float*)d_in[2];
    float* out = (float*)d_out;
    int B = in_sizes[0] / 729;
    prep_kernel<<<1, 128>>>(W1);
    sudoku_kernel<<<B, THREADS>>>(x, W2, out);
}